// round 2
// baseline (speedup 1.0000x reference)
// R1 resubmit: identical to R0 design — bench infra failed before any run.
#include <cuda_runtime.h>
#include <cstdint>

// Problem shape (fixed by the dataset): B=1, H=32, L=8192, D=128
#define NH 32
#define NL 8192
#define ND 128

// ---- output layout (float32 elements, concatenated in reference return order) ----
// kv (2,1,32,8192,128) | num_insertions (32) | pos_new (32*8192)
// kq_new (32*8192*128) | k_scales (32*8192) | k_zeros (32*8192)
// vq_new (32*8192*128) | v_scales (32*8192) | v_zeros (32*8192)
#define KV_HALF   ((size_t)NH * NL * ND)                 // 33,554,432
#define OFF_KV    ((size_t)0)
#define OFF_NI    (OFF_KV + 2 * KV_HALF)                 // 67,108,864
#define OFF_POS   (OFF_NI + NH)                          // 67,108,896
#define OFF_KQ    (OFF_POS + (size_t)NH * NL)            // 67,371,040
#define OFF_KS    (OFF_KQ + KV_HALF)                     // 100,925,472
#define OFF_KZ    (OFF_KS + (size_t)NH * NL)             // 101,187,616
#define OFF_VQ    (OFF_KZ + (size_t)NH * NL)             // 101,449,760
#define OFF_VS    (OFF_VQ + KV_HALF)                     // 135,004,192
#define OFF_VZ    (OFF_VS + (size_t)NH * NL)             // 135,266,336

__device__ unsigned long long g_evict[NH];

__global__ void init_evict_kernel() {
    if (threadIdx.x < NH) g_evict[threadIdx.x] = 0xFFFFFFFFFFFFFFFFULL;
}

// map float -> unsigned int such that uint order == float order (inf/-inf included)
__device__ __forceinline__ unsigned int orderable(float f) {
    unsigned int u = __float_as_uint(f);
    return (u & 0x80000000u) ? ~u : (u | 0x80000000u);
}

// One warp per token row. 8 warps (8 rows, same head) per block.
__global__ __launch_bounds__(256) void main_pass_kernel(
    const int*   __restrict__ kq,
    const int*   __restrict__ vq,
    const float* __restrict__ ks,
    const float* __restrict__ kz,
    const float* __restrict__ vs,
    const float* __restrict__ vz,
    const int*   __restrict__ pos,
    const float* __restrict__ w,
    float*       __restrict__ out)
{
    const int warp = threadIdx.x >> 5;
    const int lane = threadIdx.x & 31;
    const int r = blockIdx.x * 8 + warp;      // global row 0..H*L-1
    const int h = r >> 13;                    // r / 8192
    const int l = r & (NL - 1);

    const size_t rowoff = (size_t)r * ND;
    const int d0 = lane * 4;

    const int4 kqi = *(const int4*)(kq + rowoff + d0);
    const int4 vqi = *(const int4*)(vq + rowoff + d0);
    const float sk = ks[r], zk = kz[r];
    const float sv = vs[r], zv = vz[r];
    const float4 wv = *(const float4*)(w + (size_t)h * ND + d0);

    // ---- dequantize K (match jnp: mul then add, separately rounded) ----
    float k0 = __fadd_rn(__fmul_rn((float)kqi.x, sk), zk);
    float k1 = __fadd_rn(__fmul_rn((float)kqi.y, sk), zk);
    float k2 = __fadd_rn(__fmul_rn((float)kqi.z, sk), zk);
    float k3 = __fadd_rn(__fmul_rn((float)kqi.w, sk), zk);
    {
        float4 o = make_float4(k0, k1, k2, k3);
        *(float4*)(out + OFF_KV + rowoff + d0) = o;
    }

    // ---- dequantize V ----
    float v0 = __fadd_rn(__fmul_rn((float)vqi.x, sv), zv);
    float v1 = __fadd_rn(__fmul_rn((float)vqi.y, sv), zv);
    float v2 = __fadd_rn(__fmul_rn((float)vqi.z, sv), zv);
    float v3 = __fadd_rn(__fmul_rn((float)vqi.w, sv), zv);
    {
        float4 o = make_float4(v0, v1, v2, v3);
        *(float4*)(out + OFF_KV + KV_HALF + rowoff + d0) = o;
    }

    // ---- score = dot(k_row, w[h]) ----
    float dp = k0 * wv.x + k1 * wv.y + k2 * wv.z + k3 * wv.w;
    #pragma unroll
    for (int o = 16; o; o >>= 1) dp += __shfl_xor_sync(0xFFFFFFFFu, dp, o);

    // ---- requantize K: integer min/max -> dequant endpoints ----
    int kmn = min(min(kqi.x, kqi.y), min(kqi.z, kqi.w));
    int kmx = max(max(kqi.x, kqi.y), max(kqi.z, kqi.w));
    kmn = __reduce_min_sync(0xFFFFFFFFu, kmn);
    kmx = __reduce_max_sync(0xFFFFFFFFu, kmx);
    float kmnf = __fadd_rn(__fmul_rn((float)kmn, sk), zk);
    float kmxf = __fadd_rn(__fmul_rn((float)kmx, sk), zk);
    float ksn  = fmaxf(__fdiv_rn(__fsub_rn(kmxf, kmnf), 15.0f), 1e-6f);
    {
        float q0 = fminf(fmaxf(rintf(__fdiv_rn(__fsub_rn(k0, kmnf), ksn)), 0.0f), 15.0f);
        float q1 = fminf(fmaxf(rintf(__fdiv_rn(__fsub_rn(k1, kmnf), ksn)), 0.0f), 15.0f);
        float q2 = fminf(fmaxf(rintf(__fdiv_rn(__fsub_rn(k2, kmnf), ksn)), 0.0f), 15.0f);
        float q3 = fminf(fmaxf(rintf(__fdiv_rn(__fsub_rn(k3, kmnf), ksn)), 0.0f), 15.0f);
        *(float4*)(out + OFF_KQ + rowoff + d0) = make_float4(q0, q1, q2, q3);
    }

    // ---- requantize V ----
    int vmn = min(min(vqi.x, vqi.y), min(vqi.z, vqi.w));
    int vmx = max(max(vqi.x, vqi.y), max(vqi.z, vqi.w));
    vmn = __reduce_min_sync(0xFFFFFFFFu, vmn);
    vmx = __reduce_max_sync(0xFFFFFFFFu, vmx);
    float vmnf = __fadd_rn(__fmul_rn((float)vmn, sv), zv);
    float vmxf = __fadd_rn(__fmul_rn((float)vmx, sv), zv);
    float vsn  = fmaxf(__fdiv_rn(__fsub_rn(vmxf, vmnf), 15.0f), 1e-6f);
    {
        float q0 = fminf(fmaxf(rintf(__fdiv_rn(__fsub_rn(v0, vmnf), vsn)), 0.0f), 15.0f);
        float q1 = fminf(fmaxf(rintf(__fdiv_rn(__fsub_rn(v1, vmnf), vsn)), 0.0f), 15.0f);
        float q2 = fminf(fmaxf(rintf(__fdiv_rn(__fsub_rn(v2, vmnf), vsn)), 0.0f), 15.0f);
        float q3 = fminf(fmaxf(rintf(__fdiv_rn(__fsub_rn(v3, vmnf), vsn)), 0.0f), 15.0f);
        *(float4*)(out + OFF_VQ + rowoff + d0) = make_float4(q0, q1, q2, q3);
    }

    int p = 0;
    if (lane == 0) {
        p = pos[r];
        out[OFF_KS + r] = ksn;
        out[OFF_KZ + r] = kmnf;
        out[OFF_VS + r] = vsn;
        out[OFF_VZ + r] = vmnf;
        out[OFF_POS + r] = (float)p;   // copy; fixup overwrites the evicted slot
    }

    // ---- per-head argmin via packed atomicMin ----
    __shared__ unsigned long long skey[8];
    if (lane == 0) {
        float sc = dp;
        if (l < 4)   sc = __int_as_float(0x7F800000);   // +inf: protect global tokens
        if (p == -1) sc = __int_as_float(0xFF800000);   // -inf: empty slot first (overrides +inf, matching jnp order)
        skey[warp] = ((unsigned long long)orderable(sc) << 32) | (unsigned)l;
    }
    __syncthreads();
    if (warp == 0) {
        unsigned long long kk = (lane < 8) ? skey[lane] : 0xFFFFFFFFFFFFFFFFULL;
        #pragma unroll
        for (int o = 4; o; o >>= 1) {
            unsigned long long other = __shfl_xor_sync(0xFFFFFFFFu, kk, o);
            kk = (other < kk) ? other : kk;
        }
        if (lane == 0) atomicMin(&g_evict[h], kk);
    }
}

// One warp per head: overwrite the evicted row with k_val/v_val, write
// num_insertions, pos_new[evict]=input_pos, and requantize the new rows.
__global__ __launch_bounds__(32) void fixup_kernel(
    const int*   __restrict__ pos,
    const int*   __restrict__ input_pos,
    const float* __restrict__ k_val,
    const float* __restrict__ v_val,
    float*       __restrict__ out)
{
    const int h = blockIdx.x;
    const int lane = threadIdx.x;
    const unsigned long long key = g_evict[h];
    const int idx = (int)(unsigned int)(key & 0xFFFFFFFFu);
    const int r = h * NL + idx;
    const size_t rowoff = (size_t)r * ND;
    const int d0 = lane * 4;

    const int pev = pos[r];
    if (lane == 0) {
        out[OFF_NI + h]  = (pev == -1) ? 1.0f : 0.0f;
        out[OFF_POS + r] = (float)input_pos[0];
    }

    // ---- K side ----
    {
        float4 x = *(const float4*)(k_val + (size_t)h * ND + d0);
        *(float4*)(out + OFF_KV + rowoff + d0) = x;
        float mn = fminf(fminf(x.x, x.y), fminf(x.z, x.w));
        float mx = fmaxf(fmaxf(x.x, x.y), fmaxf(x.z, x.w));
        #pragma unroll
        for (int o = 16; o; o >>= 1) {
            mn = fminf(mn, __shfl_xor_sync(0xFFFFFFFFu, mn, o));
            mx = fmaxf(mx, __shfl_xor_sync(0xFFFFFFFFu, mx, o));
        }
        float sn = fmaxf(__fdiv_rn(__fsub_rn(mx, mn), 15.0f), 1e-6f);
        float q0 = fminf(fmaxf(rintf(__fdiv_rn(__fsub_rn(x.x, mn), sn)), 0.0f), 15.0f);
        float q1 = fminf(fmaxf(rintf(__fdiv_rn(__fsub_rn(x.y, mn), sn)), 0.0f), 15.0f);
        float q2 = fminf(fmaxf(rintf(__fdiv_rn(__fsub_rn(x.z, mn), sn)), 0.0f), 15.0f);
        float q3 = fminf(fmaxf(rintf(__fdiv_rn(__fsub_rn(x.w, mn), sn)), 0.0f), 15.0f);
        *(float4*)(out + OFF_KQ + rowoff + d0) = make_float4(q0, q1, q2, q3);
        if (lane == 0) { out[OFF_KS + r] = sn; out[OFF_KZ + r] = mn; }
    }

    // ---- V side ----
    {
        float4 x = *(const float4*)(v_val + (size_t)h * ND + d0);
        *(float4*)(out + OFF_KV + KV_HALF + rowoff + d0) = x;
        float mn = fminf(fminf(x.x, x.y), fminf(x.z, x.w));
        float mx = fmaxf(fmaxf(x.x, x.y), fmaxf(x.z, x.w));
        #pragma unroll
        for (int o = 16; o; o >>= 1) {
            mn = fminf(mn, __shfl_xor_sync(0xFFFFFFFFu, mn, o));
            mx = fmaxf(mx, __shfl_xor_sync(0xFFFFFFFFu, mx, o));
        }
        float sn = fmaxf(__fdiv_rn(__fsub_rn(mx, mn), 15.0f), 1e-6f);
        float q0 = fminf(fmaxf(rintf(__fdiv_rn(__fsub_rn(x.x, mn), sn)), 0.0f), 15.0f);
        float q1 = fminf(fmaxf(rintf(__fdiv_rn(__fsub_rn(x.y, mn), sn)), 0.0f), 15.0f);
        float q2 = fminf(fmaxf(rintf(__fdiv_rn(__fsub_rn(x.z, mn), sn)), 0.0f), 15.0f);
        float q3 = fminf(fmaxf(rintf(__fdiv_rn(__fsub_rn(x.w, mn), sn)), 0.0f), 15.0f);
        *(float4*)(out + OFF_VQ + rowoff + d0) = make_float4(q0, q1, q2, q3);
        if (lane == 0) { out[OFF_VS + r] = sn; out[OFF_VZ + r] = mn; }
    }
}

extern "C" void kernel_launch(void* const* d_in, const int* in_sizes, int n_in,
                              void* d_out, int out_size)
{
    // metadata order: k_cache_q, v_cache_q, k_scales, k_zeros, v_scales, v_zeros,
    //                 pos, input_pos, k_val, v_val, w
    const int*   kq  = (const int*)  d_in[0];
    const int*   vq  = (const int*)  d_in[1];
    const float* ks  = (const float*)d_in[2];
    const float* kz  = (const float*)d_in[3];
    const float* vs  = (const float*)d_in[4];
    const float* vz  = (const float*)d_in[5];
    const int*   pos = (const int*)  d_in[6];
    const int*   ip  = (const int*)  d_in[7];
    const float* kv_ = (const float*)d_in[8];
    const float* vv_ = (const float*)d_in[9];
    const float* w   = (const float*)d_in[10];
    float* out = (float*)d_out;

    init_evict_kernel<<<1, 32>>>();
    main_pass_kernel<<<(NH * NL) / 8, 256>>>(kq, vq, ks, kz, vs, vz, pos, w, out);
    fixup_kernel<<<NH, 32>>>(pos, ip, kv_, vv_, out);
}

// round 3
// speedup vs baseline: 1.0263x; 1.0263x over previous
// R3: drop init kernel + atomics (per-block partial keys, plain stores);
//     streaming cache hints (__ldcs/__stcs) on all bulk traffic.
#include <cuda_runtime.h>
#include <cstdint>

#define NH 32
#define NL 8192
#define ND 128
#define ROWS_PER_BLK 8
#define NBLK ((NH * NL) / ROWS_PER_BLK)      // 32768 blocks
#define BLK_PER_HEAD (NL / ROWS_PER_BLK)     // 1024

// ---- output layout (float32 elements, reference return order) ----
#define KV_HALF   ((size_t)NH * NL * ND)
#define OFF_KV    ((size_t)0)
#define OFF_NI    (OFF_KV + 2 * KV_HALF)
#define OFF_POS   (OFF_NI + NH)
#define OFF_KQ    (OFF_POS + (size_t)NH * NL)
#define OFF_KS    (OFF_KQ + KV_HALF)
#define OFF_KZ    (OFF_KS + (size_t)NH * NL)
#define OFF_VQ    (OFF_KZ + (size_t)NH * NL)
#define OFF_VS    (OFF_VQ + KV_HALF)
#define OFF_VZ    (OFF_VS + (size_t)NH * NL)

// per-block partial argmin keys; every slot is written every launch -> no init kernel
__device__ unsigned long long g_partial[NBLK];

// map float -> uint such that uint order == float order (handles +/-inf)
__device__ __forceinline__ unsigned int orderable(float f) {
    unsigned int u = __float_as_uint(f);
    return (u & 0x80000000u) ? ~u : (u | 0x80000000u);
}

// One warp per token row, 8 warps per block.
__global__ __launch_bounds__(256) void main_pass_kernel(
    const int*   __restrict__ kq,
    const int*   __restrict__ vq,
    const float* __restrict__ ks,
    const float* __restrict__ kz,
    const float* __restrict__ vs,
    const float* __restrict__ vz,
    const int*   __restrict__ pos,
    const float* __restrict__ w,
    float*       __restrict__ out)
{
    const int warp = threadIdx.x >> 5;
    const int lane = threadIdx.x & 31;
    const int r = blockIdx.x * ROWS_PER_BLK + warp;
    const int h = r >> 13;
    const int l = r & (NL - 1);

    const size_t rowoff = (size_t)r * ND;
    const int d0 = lane * 4;

    const int4 kqi = __ldcs((const int4*)(kq + rowoff + d0));
    const int4 vqi = __ldcs((const int4*)(vq + rowoff + d0));
    const float sk = ks[r], zk = kz[r];
    const float sv = vs[r], zv = vz[r];
    const float4 wv = *(const float4*)(w + (size_t)h * ND + d0);

    // ---- dequantize K (match jnp: mul then add, separately rounded) ----
    float k0 = __fadd_rn(__fmul_rn((float)kqi.x, sk), zk);
    float k1 = __fadd_rn(__fmul_rn((float)kqi.y, sk), zk);
    float k2 = __fadd_rn(__fmul_rn((float)kqi.z, sk), zk);
    float k3 = __fadd_rn(__fmul_rn((float)kqi.w, sk), zk);
    __stcs((float4*)(out + OFF_KV + rowoff + d0), make_float4(k0, k1, k2, k3));

    // ---- dequantize V ----
    float v0 = __fadd_rn(__fmul_rn((float)vqi.x, sv), zv);
    float v1 = __fadd_rn(__fmul_rn((float)vqi.y, sv), zv);
    float v2 = __fadd_rn(__fmul_rn((float)vqi.z, sv), zv);
    float v3 = __fadd_rn(__fmul_rn((float)vqi.w, sv), zv);
    __stcs((float4*)(out + OFF_KV + KV_HALF + rowoff + d0), make_float4(v0, v1, v2, v3));

    // ---- score = dot(k_row, w[h]) ----
    float dp = k0 * wv.x + k1 * wv.y + k2 * wv.z + k3 * wv.w;
    #pragma unroll
    for (int o = 16; o; o >>= 1) dp += __shfl_xor_sync(0xFFFFFFFFu, dp, o);

    // ---- requantize K via integer min/max (monotone affine dequant) ----
    int kmn = min(min(kqi.x, kqi.y), min(kqi.z, kqi.w));
    int kmx = max(max(kqi.x, kqi.y), max(kqi.z, kqi.w));
    kmn = __reduce_min_sync(0xFFFFFFFFu, kmn);
    kmx = __reduce_max_sync(0xFFFFFFFFu, kmx);
    float kmnf = __fadd_rn(__fmul_rn((float)kmn, sk), zk);
    float kmxf = __fadd_rn(__fmul_rn((float)kmx, sk), zk);
    float ksn  = fmaxf(__fdiv_rn(__fsub_rn(kmxf, kmnf), 15.0f), 1e-6f);
    {
        float q0 = fminf(fmaxf(rintf(__fdiv_rn(__fsub_rn(k0, kmnf), ksn)), 0.0f), 15.0f);
        float q1 = fminf(fmaxf(rintf(__fdiv_rn(__fsub_rn(k1, kmnf), ksn)), 0.0f), 15.0f);
        float q2 = fminf(fmaxf(rintf(__fdiv_rn(__fsub_rn(k2, kmnf), ksn)), 0.0f), 15.0f);
        float q3 = fminf(fmaxf(rintf(__fdiv_rn(__fsub_rn(k3, kmnf), ksn)), 0.0f), 15.0f);
        __stcs((float4*)(out + OFF_KQ + rowoff + d0), make_float4(q0, q1, q2, q3));
    }

    // ---- requantize V ----
    int vmn = min(min(vqi.x, vqi.y), min(vqi.z, vqi.w));
    int vmx = max(max(vqi.x, vqi.y), max(vqi.z, vqi.w));
    vmn = __reduce_min_sync(0xFFFFFFFFu, vmn);
    vmx = __reduce_max_sync(0xFFFFFFFFu, vmx);
    float vmnf = __fadd_rn(__fmul_rn((float)vmn, sv), zv);
    float vmxf = __fadd_rn(__fmul_rn((float)vmx, sv), zv);
    float vsn  = fmaxf(__fdiv_rn(__fsub_rn(vmxf, vmnf), 15.0f), 1e-6f);
    {
        float q0 = fminf(fmaxf(rintf(__fdiv_rn(__fsub_rn(v0, vmnf), vsn)), 0.0f), 15.0f);
        float q1 = fminf(fmaxf(rintf(__fdiv_rn(__fsub_rn(v1, vmnf), vsn)), 0.0f), 15.0f);
        float q2 = fminf(fmaxf(rintf(__fdiv_rn(__fsub_rn(v2, vmnf), vsn)), 0.0f), 15.0f);
        float q3 = fminf(fmaxf(rintf(__fdiv_rn(__fsub_rn(v3, vmnf), vsn)), 0.0f), 15.0f);
        __stcs((float4*)(out + OFF_VQ + rowoff + d0), make_float4(q0, q1, q2, q3));
    }

    int p = 0;
    if (lane == 0) {
        p = pos[r];
        out[OFF_KS + r] = ksn;
        out[OFF_KZ + r] = kmnf;
        out[OFF_VS + r] = vsn;
        out[OFF_VZ + r] = vmnf;
        out[OFF_POS + r] = (float)p;   // fixup overwrites the evicted slot
    }

    // ---- per-block partial argmin key ----
    __shared__ unsigned long long skey[ROWS_PER_BLK];
    if (lane == 0) {
        float sc = dp;
        if (l < 4)   sc = __int_as_float(0x7F800000);   // +inf: protect global tokens
        if (p == -1) sc = __int_as_float(0xFF800000);   // -inf: empty slot first
        skey[warp] = ((unsigned long long)orderable(sc) << 32) | (unsigned)l;
    }
    __syncthreads();
    if (warp == 0) {
        unsigned long long kk = (lane < ROWS_PER_BLK) ? skey[lane] : 0xFFFFFFFFFFFFFFFFULL;
        #pragma unroll
        for (int o = 4; o; o >>= 1) {
            unsigned long long other = __shfl_xor_sync(0xFFFFFFFFu, kk, o);
            kk = (other < kk) ? other : kk;
        }
        if (lane == 0) g_partial[blockIdx.x] = kk;      // plain store, no init needed
    }
}

// One block (128 threads) per head: reduce 1024 partial keys, then warp 0
// overwrites the evicted row with k_val/v_val, num_insertions, pos_new.
__global__ __launch_bounds__(128) void fixup_kernel(
    const int*   __restrict__ pos,
    const int*   __restrict__ input_pos,
    const float* __restrict__ k_val,
    const float* __restrict__ v_val,
    float*       __restrict__ out)
{
    const int h = blockIdx.x;
    const int t = threadIdx.x;
    const int lane = t & 31;
    const int wrp = t >> 5;

    __shared__ unsigned long long swk[4];
    __shared__ int sidx;

    unsigned long long kk = 0xFFFFFFFFFFFFFFFFULL;
    #pragma unroll
    for (int i = t; i < BLK_PER_HEAD; i += 128) {
        unsigned long long v = g_partial[h * BLK_PER_HEAD + i];
        kk = (v < kk) ? v : kk;
    }
    #pragma unroll
    for (int o = 16; o; o >>= 1) {
        unsigned long long other = __shfl_xor_sync(0xFFFFFFFFu, kk, o);
        kk = (other < kk) ? other : kk;
    }
    if (lane == 0) swk[wrp] = kk;
    __syncthreads();
    if (t == 0) {
        unsigned long long m = swk[0];
        #pragma unroll
        for (int i = 1; i < 4; i++) m = (swk[i] < m) ? swk[i] : m;
        sidx = (int)(unsigned int)(m & 0xFFFFFFFFu);
    }
    __syncthreads();

    if (wrp != 0) return;
    const int idx = sidx;
    const int r = h * NL + idx;
    const size_t rowoff = (size_t)r * ND;
    const int d0 = lane * 4;

    if (lane == 0) {
        out[OFF_NI + h]  = (pos[r] == -1) ? 1.0f : 0.0f;
        out[OFF_POS + r] = (float)input_pos[0];
    }

    // ---- K side ----
    {
        float4 x = *(const float4*)(k_val + (size_t)h * ND + d0);
        *(float4*)(out + OFF_KV + rowoff + d0) = x;
        float mn = fminf(fminf(x.x, x.y), fminf(x.z, x.w));
        float mx = fmaxf(fmaxf(x.x, x.y), fmaxf(x.z, x.w));
        #pragma unroll
        for (int o = 16; o; o >>= 1) {
            mn = fminf(mn, __shfl_xor_sync(0xFFFFFFFFu, mn, o));
            mx = fmaxf(mx, __shfl_xor_sync(0xFFFFFFFFu, mx, o));
        }
        float sn = fmaxf(__fdiv_rn(__fsub_rn(mx, mn), 15.0f), 1e-6f);
        float q0 = fminf(fmaxf(rintf(__fdiv_rn(__fsub_rn(x.x, mn), sn)), 0.0f), 15.0f);
        float q1 = fminf(fmaxf(rintf(__fdiv_rn(__fsub_rn(x.y, mn), sn)), 0.0f), 15.0f);
        float q2 = fminf(fmaxf(rintf(__fdiv_rn(__fsub_rn(x.z, mn), sn)), 0.0f), 15.0f);
        float q3 = fminf(fmaxf(rintf(__fdiv_rn(__fsub_rn(x.w, mn), sn)), 0.0f), 15.0f);
        *(float4*)(out + OFF_KQ + rowoff + d0) = make_float4(q0, q1, q2, q3);
        if (lane == 0) { out[OFF_KS + r] = sn; out[OFF_KZ + r] = mn; }
    }

    // ---- V side ----
    {
        float4 x = *(const float4*)(v_val + (size_t)h * ND + d0);
        *(float4*)(out + OFF_KV + KV_HALF + rowoff + d0) = x;
        float mn = fminf(fminf(x.x, x.y), fminf(x.z, x.w));
        float mx = fmaxf(fmaxf(x.x, x.y), fmaxf(x.z, x.w));
        #pragma unroll
        for (int o = 16; o; o >>= 1) {
            mn = fminf(mn, __shfl_xor_sync(0xFFFFFFFFu, mn, o));
            mx = fmaxf(mx, __shfl_xor_sync(0xFFFFFFFFu, mx, o));
        }
        float sn = fmaxf(__fdiv_rn(__fsub_rn(mx, mn), 15.0f), 1e-6f);
        float q0 = fminf(fmaxf(rintf(__fdiv_rn(__fsub_rn(x.x, mn), sn)), 0.0f), 15.0f);
        float q1 = fminf(fmaxf(rintf(__fdiv_rn(__fsub_rn(x.y, mn), sn)), 0.0f), 15.0f);
        float q2 = fminf(fmaxf(rintf(__fdiv_rn(__fsub_rn(x.z, mn), sn)), 0.0f), 15.0f);
        float q3 = fminf(fmaxf(rintf(__fdiv_rn(__fsub_rn(x.w, mn), sn)), 0.0f), 15.0f);
        *(float4*)(out + OFF_VQ + rowoff + d0) = make_float4(q0, q1, q2, q3);
        if (lane == 0) { out[OFF_VS + r] = sn; out[OFF_VZ + r] = mn; }
    }
}

extern "C" void kernel_launch(void* const* d_in, const int* in_sizes, int n_in,
                              void* d_out, int out_size)
{
    const int*   kq  = (const int*)  d_in[0];
    const int*   vq  = (const int*)  d_in[1];
    const float* ks  = (const float*)d_in[2];
    const float* kz  = (const float*)d_in[3];
    const float* vs  = (const float*)d_in[4];
    const float* vz  = (const float*)d_in[5];
    const int*   pos = (const int*)  d_in[6];
    const int*   ip  = (const int*)  d_in[7];
    const float* kv_ = (const float*)d_in[8];
    const float* vv_ = (const float*)d_in[9];
    const float* w   = (const float*)d_in[10];
    float* out = (float*)d_out;

    main_pass_kernel<<<NBLK, 256>>>(kq, vq, ks, kz, vs, vz, pos, w, out);
    fixup_kernel<<<NH, 128>>>(pos, ip, kv_, vv_, out);
}